// round 4
// baseline (speedup 1.0000x reference)
#include <cuda_runtime.h>
#include <math.h>

#define N_    2
#define L_    512
#define H_    24
#define QK_   16
#define V_    16
#define HID_  128
#define CH_   504
#define EPS_  1e-6f
#define KPAD  20

// ---------------- scratch ----------------
__device__ float g_q [N_*L_*H_*QK_];   // [n*L+i][h*16+d]
__device__ float g_kT[N_*H_*QK_*L_];   // [n][h][d][j]
__device__ float g_vT[N_*H_*V_ *L_];   // [n][h][d][j]
__device__ float g_a [N_*H_*L_*3];
__device__ float g_b [N_*H_*L_*3];
__device__ float g_cc[N_*L_*CH_];

// ---------------- f32x2 packed helpers ----------------
typedef unsigned long long u64f;
__device__ __forceinline__ u64f pk2(float lo, float hi) {
    u64f r; asm("mov.b64 %0,{%1,%2};" : "=l"(r) : "f"(lo), "f"(hi)); return r;
}
__device__ __forceinline__ void up2(u64f v, float& a, float& b) {
    asm("mov.b64 {%0,%1},%2;" : "=f"(a), "=f"(b) : "l"(v));
}
__device__ __forceinline__ u64f f2fma(u64f a, u64f b, u64f c) {
    u64f d; asm("fma.rn.f32x2 %0,%1,%2,%3;" : "=l"(d) : "l"(a), "l"(b), "l"(c)); return d;
}
__device__ __forceinline__ u64f f2mul(u64f a, u64f b) {
    u64f d; asm("mul.rn.f32x2 %0,%1,%2;" : "=l"(d) : "l"(a), "l"(b)); return d;
}
__device__ __forceinline__ u64f f2add(u64f a, u64f b) {
    u64f d; asm("add.rn.f32x2 %0,%1,%2;" : "=l"(d) : "l"(a), "l"(b)); return d;
}

// fast acos: A&S 4.4.45 3-term, |err| <= 6.8e-5 (budget 1e-3)
__device__ __forceinline__ float acos_fast(float x) {
    float y = fminf(fabsf(x), 1.0f);
    float s = sqrtf(1.0f - y);
    float p = fmaf(y, -0.0187293f, 0.0742610f);
    p = fmaf(y, p, -0.2121144f);
    p = fmaf(y, p, 1.5707288f);
    float r = s * p;
    return x < 0.f ? 3.14159265359f - r : r;
}

// ================= kernel A: fused projections =================
// C[1024 x 1296] = X[1024 x 128] @ W^T. 64x64 tile, 256 threads, 4x4/thread.
// Full K=128 resident -> single sync.
#define PJS 68
#define PJ_SMEM (2*128*PJS*4)

__global__ void __launch_bounds__(256) proj_kernel(
    const float* __restrict__ x,
    const float* __restrict__ Wq, const float* __restrict__ Wk,
    const float* __restrict__ Wv, const float* __restrict__ bv,
    const float* __restrict__ Wa, const float* __restrict__ ba,
    const float* __restrict__ Wb, const float* __restrict__ bb)
{
    extern __shared__ float psm[];
    float* xs = psm;             // [k][m]  128 x 68
    float* ws = psm + 128*PJS;   // [k][c]  128 x 68

    const int tid = threadIdx.x;
    const int rt  = blockIdx.x;  // 16 row tiles of 64
    const int ct  = blockIdx.y;  // 21 col tiles of 64

    #pragma unroll
    for (int itf = 0; itf < 8; itf++) {
        const int idx = itf*256 + tid;
        const int kq = idx & 31;
        const int m  = idx >> 5;
        const float4 v = *(const float4*)(x + (size_t)(rt*64 + m)*HID_ + kq*4);
        xs[(kq*4+0)*PJS + m] = v.x;
        xs[(kq*4+1)*PJS + m] = v.y;
        xs[(kq*4+2)*PJS + m] = v.z;
        xs[(kq*4+3)*PJS + m] = v.w;
    }
    #pragma unroll
    for (int itf = 0; itf < 8; itf++) {
        const int idx = itf*256 + tid;
        const int kq = idx & 31;
        const int cl = idx >> 5;
        const int c  = min(ct*64 + cl, 1295);
        const float* wrow;
        if      (c <  384) wrow = Wq + (size_t)c*HID_;
        else if (c <  768) wrow = Wk + (size_t)(c- 384)*HID_;
        else if (c < 1152) wrow = Wv + (size_t)(c- 768)*HID_;
        else if (c < 1224) wrow = Wa + (size_t)(c-1152)*HID_;
        else               wrow = Wb + (size_t)(c-1224)*HID_;
        const float4 v = *(const float4*)(wrow + kq*4);
        ws[(kq*4+0)*PJS + cl] = v.x;
        ws[(kq*4+1)*PJS + cl] = v.y;
        ws[(kq*4+2)*PJS + cl] = v.z;
        ws[(kq*4+3)*PJS + cl] = v.w;
    }
    __syncthreads();

    const int tx = tid & 15;
    const int ty = tid >> 4;

    float acc[4][4];
    #pragma unroll
    for (int r = 0; r < 4; r++)
        #pragma unroll
        for (int c = 0; c < 4; c++) acc[r][c] = 0.f;

    #pragma unroll 8
    for (int k = 0; k < 128; k++) {
        const float4 xv = *(const float4*)(xs + k*PJS + tx*4);
        const float4 wv = *(const float4*)(ws + k*PJS + ty*4);
        const float xa[4] = {xv.x, xv.y, xv.z, xv.w};
        const float wa[4] = {wv.x, wv.y, wv.z, wv.w};
        #pragma unroll
        for (int r = 0; r < 4; r++)
            #pragma unroll
            for (int c = 0; c < 4; c++)
                acc[r][c] = fmaf(xa[r], wa[c], acc[r][c]);
    }

    #pragma unroll
    for (int r = 0; r < 4; r++) {
        const int gi = rt*64 + tx*4 + r;
        const int n = gi >> 9, i = gi & 511;
        #pragma unroll
        for (int cv = 0; cv < 4; cv++) {
            const int c = ct*64 + ty*4 + cv;
            if (c >= 1296) continue;
            float val = acc[r][cv];
            if (c < 384) {
                g_q[(size_t)gi*384 + c] = val;
            } else if (c < 768) {
                int cc = c - 384; int h = cc >> 4, d = cc & 15;
                g_kT[((size_t)(n*H_ + h)*QK_ + d)*L_ + i] = val;
            } else if (c < 1152) {
                int cc = c - 768; int h = cc >> 4, d = cc & 15;
                g_vT[((size_t)(n*H_ + h)*V_ + d)*L_ + i] = val + bv[cc];
            } else if (c < 1224) {
                int cc = c - 1152; int h = cc/3, xx = cc - h*3;
                g_a[((size_t)(n*H_ + h)*L_ + i)*3 + xx] = val + ba[cc];
            } else {
                int cc = c - 1224; int h = cc/3, xx = cc - h*3;
                g_b[((size_t)(n*H_ + h)*L_ + i)*3 + xx] = val + bb[cc];
            }
        }
    }
}

// ================= kernel B: ray attention (f32x2 j-packed) =================
// 256 threads, 8 warps; warp handles 2 rows x 2 passes = 32 rows per block.
// Each lane processes a packed j-pair; k/v/t smem loads shared across 2 rows.
#define SM_V (L_*KPAD)
#define SM_T (SM_V + 16*L_)
#define ATTN_SMEM ((SM_T + 3*L_)*4)

__device__ __forceinline__ void attn_reduce_store(
    float av[16], float s, float ar0, float ar1, float ar2, float ath,
    int lane, float* __restrict__ cc, int h)
{
    #pragma unroll
    for (int k = 0; k < 4; k++) {
        const int half = 8 >> k;
        const bool up = (lane >> k) & 1;
        #pragma unroll
        for (int t = 0; t < half; t++) {
            float send = up ? av[t] : av[t + half];
            float recv = __shfl_xor_sync(0xffffffffu, send, 1 << k);
            av[t] = (up ? av[t + half] : av[t]) + recv;
        }
    }
    av[0] += __shfl_xor_sync(0xffffffffu, av[0], 16);

    #pragma unroll
    for (int off = 16; off > 0; off >>= 1) {
        s   += __shfl_xor_sync(0xffffffffu, s,   off);
        ar0 += __shfl_xor_sync(0xffffffffu, ar0, off);
        ar1 += __shfl_xor_sync(0xffffffffu, ar1, off);
        ar2 += __shfl_xor_sync(0xffffffffu, ar2, off);
        ath += __shfl_xor_sync(0xffffffffu, ath, off);
    }
    const float inv = 1.0f / s;
    if (lane < 16) {
        const int d = (int)(__brev((unsigned)lane) >> 28);
        cc[h*16 + d] = av[0] * inv;
    }
    if (lane == 0) {
        const float ra0 = ar0*inv, ra1 = ar1*inv, ra2 = ar2*inv;
        cc[384 + h*3 + 0] = ra0;
        cc[384 + h*3 + 1] = ra1;
        cc[384 + h*3 + 2] = ra2;
        cc[456 + h] = sqrtf(ra0*ra0 + ra1*ra1 + ra2*ra2);
        cc[480 + h] = ath*inv;
    }
}

__global__ void __launch_bounds__(256, 1) attn_kernel(
    const float* __restrict__ Rm, const float* __restrict__ t,
    const float* __restrict__ alpha, const float* __restrict__ beta)
{
    extern __shared__ float sm[];
    float* ks  = sm;            // [512][20]  (j-major, d-contiguous)
    float* vs  = sm + SM_V;     // [16][512]  (d-major, j-contiguous)
    float* txp = sm + SM_T;     // [512]
    float* typ = txp + L_;
    float* tzp = typ + L_;

    const int tid = threadIdx.x;
    const int n = blockIdx.z, h = blockIdx.y;
    const int i0 = blockIdx.x * 32;

    const float* kb = g_kT + (size_t)(n*H_ + h)*QK_*L_;
    const float* vb = g_vT + (size_t)(n*H_ + h)*V_ *L_;
    for (int idx = tid; idx < QK_*L_; idx += 256) {
        int d = idx >> 9, j = idx & 511;
        ks[j*KPAD + d] = kb[idx];
        vs[idx] = vb[idx];              // direct [d][j] copy
    }
    for (int j = tid; j < L_; j += 256) {
        const float* tp = t + (size_t)(n*L_ + j)*3;
        txp[j] = tp[0]; typ[j] = tp[1]; tzp[j] = tp[2];
    }
    __syncthreads();

    const float al = log1pf(expf(alpha[h])) * 0.70710678118f;
    const float be = log1pf(expf(beta[h]))  * 0.70710678118f;
    const float c1k = 0.70710678118f * 0.25f;
    const int warp = tid >> 5, lane = tid & 31;

    #pragma unroll 1
    for (int pass = 0; pass < 2; pass++) {
        const int iA = i0 + warp*4 + pass*2;

        u64f Rc[2][9], nc2[2][3], ac2[2][3], q2[2][8];
        float invad[2];
        #pragma unroll
        for (int r = 0; r < 2; r++) {
            const int i = iA + r;
            const float* Rp = Rm + (size_t)(n*L_ + i)*9;
            float Rv[9];
            #pragma unroll
            for (int m = 0; m < 9; m++) { Rv[m] = Rp[m]; Rc[r][m] = pk2(Rv[m], Rv[m]); }
            const float tix = txp[i], tiy = typ[i], tiz = tzp[i];
            const float* bp_ = g_b + ((size_t)(n*H_ + h)*L_ + i)*3;
            const float c0 = Rv[0]*tix + Rv[3]*tiy + Rv[6]*tiz + bp_[0];
            const float cc1 = Rv[1]*tix + Rv[4]*tiy + Rv[7]*tiz + bp_[1];
            const float c2 = Rv[2]*tix + Rv[5]*tiy + Rv[8]*tiz + bp_[2];
            nc2[r][0] = pk2(-c0, -c0); nc2[r][1] = pk2(-cc1, -cc1); nc2[r][2] = pk2(-c2, -c2);
            const float* ap = g_a + ((size_t)(n*H_ + h)*L_ + i)*3;
            const float a0 = ap[0], a1 = ap[1], a2 = ap[2];
            ac2[r][0] = pk2(a0, a0); ac2[r][1] = pk2(a1, a1); ac2[r][2] = pk2(a2, a2);
            invad[r] = 1.0f / (sqrtf(a0*a0 + a1*a1 + a2*a2) + EPS_);
            const u64f* qp = (const u64f*)(g_q + (size_t)(n*L_ + i)*(H_*QK_) + h*QK_);
            #pragma unroll
            for (int dp = 0; dp < 8; dp++) q2[r][dp] = qp[dp];
        }

        u64f av2[2][16], ps2[2], prx2[2], pry2[2], prz2[2], ath2[2];
        const u64f z2 = pk2(0.f, 0.f);
        #pragma unroll
        for (int r = 0; r < 2; r++) {
            #pragma unroll
            for (int d = 0; d < 16; d++) av2[r][d] = z2;
            ps2[r] = z2; prx2[r] = z2; pry2[r] = z2; prz2[r] = z2; ath2[r] = z2;
        }

        #pragma unroll 1
        for (int it = 0; it < 8; it++) {
            const int j0 = it*64 + lane*2;
            const u64f tx2 = *(const u64f*)(txp + j0);
            const u64f ty2 = *(const u64f*)(typ + j0);
            const u64f tz2 = *(const u64f*)(tzp + j0);
            const u64f* k0p = (const u64f*)(ks + j0*KPAD);
            const u64f* k1p = (const u64f*)(ks + (j0+1)*KPAD);
            u64f ka[8], kbp[8];
            #pragma unroll
            for (int m = 0; m < 8; m++) { ka[m] = k0p[m]; kbp[m] = k1p[m]; }

            u64f p2s[2];
            #pragma unroll
            for (int r = 0; r < 2; r++) {
                u64f rx2 = f2fma(Rc[r][0], tx2, f2fma(Rc[r][3], ty2, f2fma(Rc[r][6], tz2, nc2[r][0])));
                u64f ry2 = f2fma(Rc[r][1], tx2, f2fma(Rc[r][4], ty2, f2fma(Rc[r][7], tz2, nc2[r][1])));
                u64f rz2 = f2fma(Rc[r][2], tx2, f2fma(Rc[r][5], ty2, f2fma(Rc[r][8], tz2, nc2[r][2])));
                u64f rr2  = f2fma(rx2, rx2, f2fma(ry2, ry2, f2mul(rz2, rz2)));
                u64f rda2 = f2fma(rx2, ac2[r][0], f2fma(ry2, ac2[r][1], f2mul(rz2, ac2[r][2])));
                float rr0, rr1, rda0, rda1;
                up2(rr2, rr0, rr1); up2(rda2, rda0, rda1);
                rr0 = fmaxf(rr0, 1e-24f); rr1 = fmaxf(rr1, 1e-24f);
                const float ir0 = rsqrtf(rr0), ir1 = rsqrtf(rr1);
                const float rs0 = rr0*ir0, rs1 = rr1*ir1;
                const float th0 = acos_fast(rda0*ir0*invad[r]);
                const float th1 = acos_fast(rda1*ir1*invad[r]);

                u64f s2a = f2mul(q2[r][0], ka[0]);
                u64f s2b = f2mul(q2[r][0], kbp[0]);
                #pragma unroll
                for (int m = 1; m < 8; m++) {
                    s2a = f2fma(q2[r][m], ka[m], s2a);
                    s2b = f2fma(q2[r][m], kbp[m], s2b);
                }
                float sa0, sa1, sb0, sb1;
                up2(s2a, sa0, sa1); up2(s2b, sb0, sb1);
                const float st0 = sa0 + sa1, st1 = sb0 + sb1;

                float lg0 = fmaf(c1k, st0, fmaf(-al, rs0, fmaf(-be, th0, -4.f)));
                float lg1 = fmaf(c1k, st1, fmaf(-al, rs1, fmaf(-be, th1, -4.f)));
                const int i_r = iA + r;
                if (j0     == i_r) lg0 = -104.f;
                if (j0 + 1 == i_r) lg1 = -104.f;
                const float p0 = __expf(lg0), p1 = __expf(lg1);
                const u64f p2 = pk2(p0, p1);
                p2s[r] = p2;
                ps2[r]  = f2add(ps2[r], p2);
                prx2[r] = f2fma(p2, rx2, prx2[r]);
                pry2[r] = f2fma(p2, ry2, pry2[r]);
                prz2[r] = f2fma(p2, rz2, prz2[r]);
                ath2[r] = f2fma(p2, pk2(th0, th1), ath2[r]);
            }

            #pragma unroll
            for (int d = 0; d < 16; d++) {
                const u64f v2 = *(const u64f*)(vs + d*L_ + j0);
                av2[0][d] = f2fma(p2s[0], v2, av2[0][d]);
                av2[1][d] = f2fma(p2s[1], v2, av2[1][d]);
            }
        }

        #pragma unroll
        for (int r = 0; r < 2; r++) {
            float av[16];
            #pragma unroll
            for (int d = 0; d < 16; d++) { float x, y; up2(av2[r][d], x, y); av[d] = x + y; }
            float x, y;
            up2(ps2[r],  x, y); const float s   = x + y;
            up2(prx2[r], x, y); const float ar0 = x + y;
            up2(pry2[r], x, y); const float ar1 = x + y;
            up2(prz2[r], x, y); const float ar2 = x + y;
            up2(ath2[r], x, y); const float ath = x + y;
            float* cc = g_cc + (size_t)(n*L_ + iA + r)*CH_;
            attn_reduce_store(av, s, ar0, ar1, ar2, ath, lane, cc, h);
        }
    }
}

// ================= kernel C: output projection =================
__global__ void out_kernel(const float* __restrict__ Wp, const float* __restrict__ bp,
                           float* __restrict__ out)
{
    __shared__ __align__(16) float cs[8*CH_];
    const int tid = threadIdx.x;
    const int r0 = blockIdx.x * 8;

    for (int idx = tid; idx < 8*CH_; idx += 128)
        cs[idx] = g_cc[(size_t)r0*CH_ + idx];
    __syncthreads();

    float acc[8];
    #pragma unroll
    for (int r = 0; r < 8; r++) acc[r] = 0.f;

    const float4* w4 = (const float4*)(Wp + (size_t)tid*CH_);
    #pragma unroll 2
    for (int k4 = 0; k4 < CH_/4; k4++) {
        const float4 w = w4[k4];
        #pragma unroll
        for (int r = 0; r < 8; r++) {
            const float4 cv = ((const float4*)(cs + r*CH_))[k4];
            acc[r] += cv.x*w.x + cv.y*w.y + cv.z*w.z + cv.w*w.w;
        }
    }
    const float bbv = bp[tid];
    #pragma unroll
    for (int r = 0; r < 8; r++)
        out[(size_t)(r0 + r)*HID_ + tid] = acc[r] + bbv;
}

// ---------------- launch ----------------
extern "C" void kernel_launch(void* const* d_in, const int* in_sizes, int n_in,
                              void* d_out, int out_size)
{
    const float* x     = (const float*)d_in[0];
    const float* R     = (const float*)d_in[1];
    const float* t     = (const float*)d_in[2];
    const float* Wq    = (const float*)d_in[4];
    const float* Wk    = (const float*)d_in[5];
    const float* Wv    = (const float*)d_in[6];
    const float* bv    = (const float*)d_in[7];
    const float* Wa    = (const float*)d_in[8];
    const float* ba    = (const float*)d_in[9];
    const float* Wb    = (const float*)d_in[10];
    const float* bb    = (const float*)d_in[11];
    const float* Wp    = (const float*)d_in[12];
    const float* bp    = (const float*)d_in[13];
    const float* alpha = (const float*)d_in[14];
    const float* beta  = (const float*)d_in[15];

    cudaFuncSetAttribute(proj_kernel, cudaFuncAttributeMaxDynamicSharedMemorySize, PJ_SMEM);
    proj_kernel<<<dim3(16, 21), 256, PJ_SMEM>>>(x, Wq, Wk, Wv, bv, Wa, ba, Wb, bb);

    cudaFuncSetAttribute(attn_kernel, cudaFuncAttributeMaxDynamicSharedMemorySize, ATTN_SMEM);
    attn_kernel<<<dim3(16, H_, N_), 256, ATTN_SMEM>>>(R, t, alpha, beta);

    out_kernel<<<dim3(128), 128>>>(Wp, bp, (float*)d_out);
}

// round 6
// speedup vs baseline: 1.1104x; 1.1104x over previous
#include <cuda_runtime.h>
#include <math.h>

#define N_    2
#define L_    512
#define H_    24
#define QK_   16
#define V_    16
#define HID_  128
#define CH_   504
#define EPS_  1e-6f
#define KPAD  20

// ---------------- scratch ----------------
__device__ float g_q [N_*L_*H_*QK_];   // [n*L+i][h*16+d]
__device__ float g_kT[N_*H_*QK_*L_];   // [n][h][d][j]
__device__ float g_vT[N_*H_*V_ *L_];   // [n][h][d][j]
__device__ float g_a [N_*H_*L_*3];
__device__ float g_b [N_*H_*L_*3];
__device__ float g_cc[N_*L_*CH_];

__device__ __forceinline__ float rsqrt_fast(float x) {
    float r; asm("rsqrt.approx.f32 %0,%1;" : "=f"(r) : "f"(x)); return r;
}
// fast acos: A&S 4.4.45 3-term, |err| <= 6.8e-5 (budget 1e-3)
__device__ __forceinline__ float acos_fast(float x) {
    float ax = fabsf(x);
    float s; asm("sqrt.approx.f32 %0,%1;" : "=f"(s) : "f"(1.0f - ax));
    float p = fmaf(ax, -0.0187293f, 0.0742610f);
    p = fmaf(ax, p, -0.2121144f);
    p = fmaf(ax, p, 1.5707288f);
    float r = s * p;
    return x < 0.f ? 3.14159265359f - r : r;
}

// ================= kernel A: fused projections =================
// C[1024 x 1296] = X[1024 x 128] @ W^T. 32x64 tile, 256 threads, 2x4/thread,
// K chunked by 64. grid 32x21 = 672 blocks.
__global__ void __launch_bounds__(256) proj_kernel(
    const float* __restrict__ x,
    const float* __restrict__ Wq, const float* __restrict__ Wk,
    const float* __restrict__ Wv, const float* __restrict__ bv,
    const float* __restrict__ Wa, const float* __restrict__ ba,
    const float* __restrict__ Wb, const float* __restrict__ bb)
{
    __shared__ float xs[64*36];   // [k][m]  m=0..31
    __shared__ float ws[64*68];   // [k][c]  c=0..63

    const int tid = threadIdx.x;
    const int rt  = blockIdx.x;   // 32 row tiles of 32
    const int ct  = blockIdx.y;   // 21 col tiles of 64

    const int tx = tid & 15;      // col group (4 cols)
    const int ty = tid >> 4;      // row group (2 rows)

    float acc[2][4];
    #pragma unroll
    for (int r = 0; r < 2; r++)
        #pragma unroll
        for (int c = 0; c < 4; c++) acc[r][c] = 0.f;

    #pragma unroll 1
    for (int chunk = 0; chunk < 2; chunk++) {
        __syncthreads();
        #pragma unroll
        for (int itf = 0; itf < 2; itf++) {
            const int idx = itf*256 + tid;
            const int kq = idx & 15;
            const int m  = idx >> 4;
            const float4 v = *(const float4*)(x + (size_t)(rt*32 + m)*HID_ + chunk*64 + kq*4);
            xs[(kq*4+0)*36 + m] = v.x;
            xs[(kq*4+1)*36 + m] = v.y;
            xs[(kq*4+2)*36 + m] = v.z;
            xs[(kq*4+3)*36 + m] = v.w;
        }
        #pragma unroll
        for (int itf = 0; itf < 4; itf++) {
            const int idx = itf*256 + tid;
            const int kq = idx & 15;
            const int cl = idx >> 4;
            const int c  = min(ct*64 + cl, 1295);
            const float* wrow;
            if      (c <  384) wrow = Wq + (size_t)c*HID_;
            else if (c <  768) wrow = Wk + (size_t)(c- 384)*HID_;
            else if (c < 1152) wrow = Wv + (size_t)(c- 768)*HID_;
            else if (c < 1224) wrow = Wa + (size_t)(c-1152)*HID_;
            else               wrow = Wb + (size_t)(c-1224)*HID_;
            const float4 v = *(const float4*)(wrow + chunk*64 + kq*4);
            ws[(kq*4+0)*68 + cl] = v.x;
            ws[(kq*4+1)*68 + cl] = v.y;
            ws[(kq*4+2)*68 + cl] = v.z;
            ws[(kq*4+3)*68 + cl] = v.w;
        }
        __syncthreads();

        #pragma unroll 8
        for (int k = 0; k < 64; k++) {
            const float2 xv = *(const float2*)(xs + k*36 + ty*2);
            const float4 wv = *(const float4*)(ws + k*68 + tx*4);
            acc[0][0] = fmaf(xv.x, wv.x, acc[0][0]);
            acc[0][1] = fmaf(xv.x, wv.y, acc[0][1]);
            acc[0][2] = fmaf(xv.x, wv.z, acc[0][2]);
            acc[0][3] = fmaf(xv.x, wv.w, acc[0][3]);
            acc[1][0] = fmaf(xv.y, wv.x, acc[1][0]);
            acc[1][1] = fmaf(xv.y, wv.y, acc[1][1]);
            acc[1][2] = fmaf(xv.y, wv.z, acc[1][2]);
            acc[1][3] = fmaf(xv.y, wv.w, acc[1][3]);
        }
    }

    #pragma unroll
    for (int r = 0; r < 2; r++) {
        const int gi = rt*32 + ty*2 + r;
        const int n = gi >> 9, i = gi & 511;
        #pragma unroll
        for (int cv = 0; cv < 4; cv++) {
            const int c = ct*64 + tx*4 + cv;
            if (c >= 1296) continue;
            float val = acc[r][cv];
            if (c < 384) {
                g_q[(size_t)gi*384 + c] = val;
            } else if (c < 768) {
                int cc = c - 384; int h = cc >> 4, d = cc & 15;
                g_kT[((size_t)(n*H_ + h)*QK_ + d)*L_ + i] = val;
            } else if (c < 1152) {
                int cc = c - 768; int h = cc >> 4, d = cc & 15;
                g_vT[((size_t)(n*H_ + h)*V_ + d)*L_ + i] = val + bv[cc];
            } else if (c < 1224) {
                int cc = c - 1152; int h = cc/3, xx = cc - h*3;
                g_a[((size_t)(n*H_ + h)*L_ + i)*3 + xx] = val + ba[cc];
            } else {
                int cc = c - 1224; int h = cc/3, xx = cc - h*3;
                g_b[((size_t)(n*H_ + h)*L_ + i)*3 + xx] = val + bb[cc];
            }
        }
    }
}

// ================= kernel B: ray attention (R3 structure + fast math) =================
// 512 threads, 64 i-rows/block. Warp runs 2 rows concurrently; explicit
// per-element rotation (R is a general 3x3 matrix, NOT orthogonal).
// Fixed softmax max M0=4 (ray_w <= 0, |std| small) -> single __expf.
__device__ __forceinline__ void attn_reduce_store(
    float av[16], float s, float ar0, float ar1, float ar2, float ath,
    int lane, float* __restrict__ cc, int h)
{
    #pragma unroll
    for (int k = 0; k < 4; k++) {
        const int half = 8 >> k;
        const bool up = (lane >> k) & 1;
        #pragma unroll
        for (int t = 0; t < half; t++) {
            float send = up ? av[t] : av[t + half];
            float recv = __shfl_xor_sync(0xffffffffu, send, 1 << k);
            av[t] = (up ? av[t + half] : av[t]) + recv;
        }
    }
    av[0] += __shfl_xor_sync(0xffffffffu, av[0], 16);

    #pragma unroll
    for (int off = 16; off > 0; off >>= 1) {
        s   += __shfl_xor_sync(0xffffffffu, s,   off);
        ar0 += __shfl_xor_sync(0xffffffffu, ar0, off);
        ar1 += __shfl_xor_sync(0xffffffffu, ar1, off);
        ar2 += __shfl_xor_sync(0xffffffffu, ar2, off);
        ath += __shfl_xor_sync(0xffffffffu, ath, off);
    }
    const float inv = 1.0f / s;
    if (lane < 16) {
        const int d = (int)(__brev((unsigned)lane) >> 28);
        cc[h*16 + d] = av[0] * inv;
    }
    if (lane == 0) {
        const float ra0 = ar0*inv, ra1 = ar1*inv, ra2 = ar2*inv;
        cc[384 + h*3 + 0] = ra0;
        cc[384 + h*3 + 1] = ra1;
        cc[384 + h*3 + 2] = ra2;
        cc[456 + h] = sqrtf(ra0*ra0 + ra1*ra1 + ra2*ra2);
        cc[480 + h] = ath*inv;
    }
}

__global__ void __launch_bounds__(512, 1) attn_kernel(
    const float* __restrict__ Rm, const float* __restrict__ t,
    const float* __restrict__ alpha, const float* __restrict__ beta)
{
    extern __shared__ float sm[];
    float*  ks  = sm;                       // [512][20]
    float*  vs  = sm + L_*KPAD;             // [512][20]
    float4* ts4 = (float4*)(sm + 2*L_*KPAD);

    const int tid = threadIdx.x;
    const int n = blockIdx.z, h = blockIdx.y;
    const int i0 = blockIdx.x * 64;

    const float* kb = g_kT + (size_t)(n*H_ + h)*QK_*L_;
    const float* vb = g_vT + (size_t)(n*H_ + h)*V_ *L_;
    for (int idx = tid; idx < QK_*L_; idx += 512) {
        int d = idx >> 9, j = idx & 511;
        ks[j*KPAD + d] = kb[idx];
        vs[j*KPAD + d] = vb[idx];
    }
    for (int j = tid; j < L_; j += 512) {
        const float* tp = t + (n*L_ + j)*3;
        ts4[j] = make_float4(tp[0], tp[1], tp[2], 0.f);
    }
    __syncthreads();

    const float al = log1pf(expf(alpha[h])) * 0.70710678118f;
    const float be = log1pf(expf(beta[h]))  * 0.70710678118f;
    const float c1 = 0.70710678118f * 0.25f;
    const int warp = tid >> 5, lane = tid & 31;

    #pragma unroll 1
    for (int pass = 0; pass < 2; pass++) {
        const int iA = i0 + warp*4 + pass*2;
        const int iB = iA + 1;

        const float4* qpA = (const float4*)(g_q + (size_t)(n*L_ + iA)*(H_*QK_) + h*QK_);
        const float4 qA0 = qpA[0], qA1 = qpA[1], qA2 = qpA[2], qA3 = qpA[3];
        const float4* qpB = (const float4*)(g_q + (size_t)(n*L_ + iB)*(H_*QK_) + h*QK_);
        const float4 qB0 = qpB[0], qB1 = qpB[1], qB2 = qpB[2], qB3 = qpB[3];

        const float* RA = Rm + (size_t)(n*L_ + iA)*9;
        const float A00=RA[0],A01=RA[1],A02=RA[2],A10=RA[3],A11=RA[4],A12=RA[5],A20=RA[6],A21=RA[7],A22=RA[8];
        const float* RB = Rm + (size_t)(n*L_ + iB)*9;
        const float B00=RB[0],B01=RB[1],B02=RB[2],B10=RB[3],B11=RB[4],B12=RB[5],B20=RB[6],B21=RB[7],B22=RB[8];

        const float4 tiA = ts4[iA], tiB = ts4[iB];

        const float* apA = g_a + ((size_t)(n*H_ + h)*L_ + iA)*3;
        const float aA0=apA[0], aA1=apA[1], aA2=apA[2];
        const float* apB = g_a + ((size_t)(n*H_ + h)*L_ + iB)*3;
        const float aB0=apB[0], aB1=apB[1], aB2=apB[2];
        const float invadA = 1.0f/(sqrtf(aA0*aA0+aA1*aA1+aA2*aA2) + EPS_);
        const float invadB = 1.0f/(sqrtf(aB0*aB0+aB1*aB1+aB2*aB2) + EPS_);

        const float* bpA = g_b + ((size_t)(n*H_ + h)*L_ + iA)*3;
        const float* bpB = g_b + ((size_t)(n*H_ + h)*L_ + iB)*3;
        const float cA0 = A00*tiA.x + A10*tiA.y + A20*tiA.z + bpA[0];
        const float cA1 = A01*tiA.x + A11*tiA.y + A21*tiA.z + bpA[1];
        const float cA2 = A02*tiA.x + A12*tiA.y + A22*tiA.z + bpA[2];
        const float cB0 = B00*tiB.x + B10*tiB.y + B20*tiB.z + bpB[0];
        const float cB1 = B01*tiB.x + B11*tiB.y + B21*tiB.z + bpB[1];
        const float cB2 = B02*tiB.x + B12*tiB.y + B22*tiB.z + bpB[2];

        float sA=0.f, arA0=0.f, arA1=0.f, arA2=0.f, athA=0.f;
        float sB=0.f, arB0=0.f, arB1=0.f, arB2=0.f, athB=0.f;
        float avA[16], avB[16];
        #pragma unroll
        for (int d = 0; d < 16; d++) { avA[d]=0.f; avB[d]=0.f; }

        #pragma unroll 1
        for (int it = 0; it < 16; it++) {
            const int j = it*32 + lane;
            const float4 tj = ts4[j];

            const float rxA = fmaf(A20,tj.z, fmaf(A10,tj.y, fmaf(A00,tj.x, -cA0)));
            const float ryA = fmaf(A21,tj.z, fmaf(A11,tj.y, fmaf(A01,tj.x, -cA1)));
            const float rzA = fmaf(A22,tj.z, fmaf(A12,tj.y, fmaf(A02,tj.x, -cA2)));
            float rrA = fmaf(rxA,rxA, fmaf(ryA,ryA, rzA*rzA));
            rrA = fmaxf(rrA, 1e-24f);
            const float irA = rsqrt_fast(rrA);
            const float rsA = rrA * irA;
            const float rdaA = fmaf(rxA,aA0, fmaf(ryA,aA1, rzA*aA2));
            float ctA = rdaA * irA * invadA;
            ctA = fminf(1.f, fmaxf(-1.f, ctA));
            const float thA = acos_fast(ctA);

            const float rxB = fmaf(B20,tj.z, fmaf(B10,tj.y, fmaf(B00,tj.x, -cB0)));
            const float ryB = fmaf(B21,tj.z, fmaf(B11,tj.y, fmaf(B01,tj.x, -cB1)));
            const float rzB = fmaf(B22,tj.z, fmaf(B12,tj.y, fmaf(B02,tj.x, -cB2)));
            float rrB = fmaf(rxB,rxB, fmaf(ryB,ryB, rzB*rzB));
            rrB = fmaxf(rrB, 1e-24f);
            const float irB = rsqrt_fast(rrB);
            const float rsB = rrB * irB;
            const float rdaB = fmaf(rxB,aB0, fmaf(ryB,aB1, rzB*aB2));
            float ctB = rdaB * irB * invadB;
            ctB = fminf(1.f, fmaxf(-1.f, ctB));
            const float thB = acos_fast(ctB);

            const float4* kj = (const float4*)(ks + j*KPAD);
            const float4 k0 = kj[0], k1 = kj[1], k2 = kj[2], k3 = kj[3];
            float stA = qA0.x*k0.x + qA0.y*k0.y + qA0.z*k0.z + qA0.w*k0.w
                      + qA1.x*k1.x + qA1.y*k1.y + qA1.z*k1.z + qA1.w*k1.w
                      + qA2.x*k2.x + qA2.y*k2.y + qA2.z*k2.z + qA2.w*k2.w
                      + qA3.x*k3.x + qA3.y*k3.y + qA3.z*k3.z + qA3.w*k3.w;
            float stB = qB0.x*k0.x + qB0.y*k0.y + qB0.z*k0.z + qB0.w*k0.w
                      + qB1.x*k1.x + qB1.y*k1.y + qB1.z*k1.z + qB1.w*k1.w
                      + qB2.x*k2.x + qB2.y*k2.y + qB2.z*k2.z + qB2.w*k2.w
                      + qB3.x*k3.x + qB3.y*k3.y + qB3.z*k3.z + qB3.w*k3.w;

            float argA = fmaf(c1, stA, fmaf(-al, rsA, fmaf(-be, thA, -4.f)));
            float argB = fmaf(c1, stB, fmaf(-al, rsB, fmaf(-be, thB, -4.f)));
            if (j == iA) argA = -104.f;
            if (j == iB) argB = -104.f;
            const float pA = __expf(argA);
            const float pB = __expf(argB);

            const float4* vj = (const float4*)(vs + j*KPAD);
            const float4 v0 = vj[0], v1 = vj[1], v2 = vj[2], v3 = vj[3];

            sA += pA; sB += pB;
            avA[0]=fmaf(pA,v0.x,avA[0]); avA[1]=fmaf(pA,v0.y,avA[1]); avA[2]=fmaf(pA,v0.z,avA[2]); avA[3]=fmaf(pA,v0.w,avA[3]);
            avA[4]=fmaf(pA,v1.x,avA[4]); avA[5]=fmaf(pA,v1.y,avA[5]); avA[6]=fmaf(pA,v1.z,avA[6]); avA[7]=fmaf(pA,v1.w,avA[7]);
            avA[8]=fmaf(pA,v2.x,avA[8]); avA[9]=fmaf(pA,v2.y,avA[9]); avA[10]=fmaf(pA,v2.z,avA[10]); avA[11]=fmaf(pA,v2.w,avA[11]);
            avA[12]=fmaf(pA,v3.x,avA[12]); avA[13]=fmaf(pA,v3.y,avA[13]); avA[14]=fmaf(pA,v3.z,avA[14]); avA[15]=fmaf(pA,v3.w,avA[15]);
            avB[0]=fmaf(pB,v0.x,avB[0]); avB[1]=fmaf(pB,v0.y,avB[1]); avB[2]=fmaf(pB,v0.z,avB[2]); avB[3]=fmaf(pB,v0.w,avB[3]);
            avB[4]=fmaf(pB,v1.x,avB[4]); avB[5]=fmaf(pB,v1.y,avB[5]); avB[6]=fmaf(pB,v1.z,avB[6]); avB[7]=fmaf(pB,v1.w,avB[7]);
            avB[8]=fmaf(pB,v2.x,avB[8]); avB[9]=fmaf(pB,v2.y,avB[9]); avB[10]=fmaf(pB,v2.z,avB[10]); avB[11]=fmaf(pB,v2.w,avB[11]);
            avB[12]=fmaf(pB,v3.x,avB[12]); avB[13]=fmaf(pB,v3.y,avB[13]); avB[14]=fmaf(pB,v3.z,avB[14]); avB[15]=fmaf(pB,v3.w,avB[15]);

            arA0=fmaf(pA,rxA,arA0); arA1=fmaf(pA,ryA,arA1); arA2=fmaf(pA,rzA,arA2); athA=fmaf(pA,thA,athA);
            arB0=fmaf(pB,rxB,arB0); arB1=fmaf(pB,ryB,arB1); arB2=fmaf(pB,rzB,arB2); athB=fmaf(pB,thB,athB);
        }

        float* ccA = g_cc + (size_t)(n*L_ + iA)*CH_;
        float* ccB = g_cc + (size_t)(n*L_ + iB)*CH_;
        attn_reduce_store(avA, sA, arA0, arA1, arA2, athA, lane, ccA, h);
        attn_reduce_store(avB, sB, arB0, arB1, arB2, athB, lane, ccB, h);
    }
}

// ================= kernel C: output projection =================
__global__ void out_kernel(const float* __restrict__ Wp, const float* __restrict__ bp,
                           float* __restrict__ out)
{
    __shared__ __align__(16) float cs[8*CH_];
    const int tid = threadIdx.x;
    const int r0 = blockIdx.x * 8;

    for (int idx = tid; idx < 8*CH_; idx += 128)
        cs[idx] = g_cc[(size_t)r0*CH_ + idx];
    __syncthreads();

    float acc[8];
    #pragma unroll
    for (int r = 0; r < 8; r++) acc[r] = 0.f;

    const float4* w4 = (const float4*)(Wp + (size_t)tid*CH_);
    #pragma unroll 2
    for (int k4 = 0; k4 < CH_/4; k4++) {
        const float4 w = w4[k4];
        #pragma unroll
        for (int r = 0; r < 8; r++) {
            const float4 cv = ((const float4*)(cs + r*CH_))[k4];
            acc[r] += cv.x*w.x + cv.y*w.y + cv.z*w.z + cv.w*w.w;
        }
    }
    const float bbv = bp[tid];
    #pragma unroll
    for (int r = 0; r < 8; r++)
        out[(size_t)(r0 + r)*HID_ + tid] = acc[r] + bbv;
}

// ---------------- launch ----------------
extern "C" void kernel_launch(void* const* d_in, const int* in_sizes, int n_in,
                              void* d_out, int out_size)
{
    const float* x     = (const float*)d_in[0];
    const float* R     = (const float*)d_in[1];
    const float* t     = (const float*)d_in[2];
    const float* Wq    = (const float*)d_in[4];
    const float* Wk    = (const float*)d_in[5];
    const float* Wv    = (const float*)d_in[6];
    const float* bv    = (const float*)d_in[7];
    const float* Wa    = (const float*)d_in[8];
    const float* ba    = (const float*)d_in[9];
    const float* Wb    = (const float*)d_in[10];
    const float* bb    = (const float*)d_in[11];
    const float* Wp    = (const float*)d_in[12];
    const float* bp    = (const float*)d_in[13];
    const float* alpha = (const float*)d_in[14];
    const float* beta  = (const float*)d_in[15];

    proj_kernel<<<dim3(32, 21), 256>>>(x, Wq, Wk, Wv, bv, Wa, ba, Wb, bb);

    const int smem = (2*L_*KPAD + L_*4) * (int)sizeof(float);  // 90112 B
    cudaFuncSetAttribute(attn_kernel, cudaFuncAttributeMaxDynamicSharedMemorySize, smem);
    attn_kernel<<<dim3(8, H_, N_), 512, smem>>>(R, t, alpha, beta);

    out_kernel<<<dim3(128), 128>>>(Wp, bp, (float*)d_out);
}

// round 7
// speedup vs baseline: 1.1897x; 1.0714x over previous
#include <cuda_runtime.h>
#include <math.h>

#define N_    2
#define L_    512
#define H_    24
#define QK_   16
#define V_    16
#define HID_  128
#define CH_   504
#define EPS_  1e-6f
#define KPAD  20

// ---------------- scratch ----------------
__device__ float g_q [N_*L_*H_*QK_];   // [n*L+i][h*16+d]
__device__ float g_kT[N_*H_*QK_*L_];   // [n][h][d][j]
__device__ float g_vT[N_*H_*V_ *L_];   // [n][h][d][j]
__device__ float g_a [N_*H_*L_*3];
__device__ float g_b [N_*H_*L_*3];
__device__ float g_cc[N_*L_*CH_];

__device__ __forceinline__ float rsqrt_fast(float x) {
    float r; asm("rsqrt.approx.f32 %0,%1;" : "=f"(r) : "f"(x)); return r;
}
__device__ __forceinline__ float ex2_fast(float x) {
    float r; asm("ex2.approx.f32 %0,%1;" : "=f"(r) : "f"(x)); return r;
}
// fast acos with built-in clamp: A&S 4.4.45, |err| <= 6.8e-5 (budget 1e-3)
__device__ __forceinline__ float acos_fast(float x) {
    float ax = fminf(fabsf(x), 1.0f);
    float s; asm("sqrt.approx.f32 %0,%1;" : "=f"(s) : "f"(1.0f - ax));
    float p = fmaf(ax, -0.0187293f, 0.0742610f);
    p = fmaf(ax, p, -0.2121144f);
    p = fmaf(ax, p, 1.5707288f);
    float r = s * p;
    return x < 0.f ? 3.14159265359f - r : r;
}

// ================= kernel A: fused projections (R3 proven, 22us) =================
#define PJS 68

__global__ void __launch_bounds__(256) proj_kernel(
    const float* __restrict__ x,
    const float* __restrict__ Wq, const float* __restrict__ Wk,
    const float* __restrict__ Wv, const float* __restrict__ bv,
    const float* __restrict__ Wa, const float* __restrict__ ba,
    const float* __restrict__ Wb, const float* __restrict__ bb)
{
    __shared__ float xs[32*PJS];   // [k][m]
    __shared__ float ws[32*PJS];   // [k][c_local]

    const int tid = threadIdx.x;
    const int rt  = blockIdx.x;    // 16 row tiles of 64
    const int ct  = blockIdx.y;    // 21 col tiles of 64

    const int tx = tid & 15;
    const int ty = tid >> 4;

    float acc[4][4];
    #pragma unroll
    for (int r = 0; r < 4; r++)
        #pragma unroll
        for (int c = 0; c < 4; c++) acc[r][c] = 0.f;

    #pragma unroll 1
    for (int chunk = 0; chunk < 4; chunk++) {
        __syncthreads();
        #pragma unroll
        for (int it = 0; it < 2; it++) {
            const int idx = it*256 + tid;
            const int kq = idx & 7;
            const int m  = idx >> 3;
            const float4 v = *(const float4*)(x + (size_t)(rt*64 + m)*HID_ + chunk*32 + kq*4);
            xs[(kq*4+0)*PJS + m] = v.x;
            xs[(kq*4+1)*PJS + m] = v.y;
            xs[(kq*4+2)*PJS + m] = v.z;
            xs[(kq*4+3)*PJS + m] = v.w;
        }
        #pragma unroll
        for (int it = 0; it < 2; it++) {
            const int idx = it*256 + tid;
            const int kq = idx & 7;
            const int cl = idx >> 3;
            const int c  = min(ct*64 + cl, 1295);
            const float* wrow;
            if      (c <  384) wrow = Wq + (size_t)c*HID_;
            else if (c <  768) wrow = Wk + (size_t)(c- 384)*HID_;
            else if (c < 1152) wrow = Wv + (size_t)(c- 768)*HID_;
            else if (c < 1224) wrow = Wa + (size_t)(c-1152)*HID_;
            else               wrow = Wb + (size_t)(c-1224)*HID_;
            const float4 v = *(const float4*)(wrow + chunk*32 + kq*4);
            ws[(kq*4+0)*PJS + cl] = v.x;
            ws[(kq*4+1)*PJS + cl] = v.y;
            ws[(kq*4+2)*PJS + cl] = v.z;
            ws[(kq*4+3)*PJS + cl] = v.w;
        }
        __syncthreads();

        #pragma unroll
        for (int k = 0; k < 32; k++) {
            const float4 xv = *(const float4*)(xs + k*PJS + tx*4);
            const float4 wv = *(const float4*)(ws + k*PJS + ty*4);
            const float xa[4] = {xv.x, xv.y, xv.z, xv.w};
            const float wa[4] = {wv.x, wv.y, wv.z, wv.w};
            #pragma unroll
            for (int r = 0; r < 4; r++)
                #pragma unroll
                for (int c = 0; c < 4; c++)
                    acc[r][c] = fmaf(xa[r], wa[c], acc[r][c]);
        }
    }

    #pragma unroll
    for (int r = 0; r < 4; r++) {
        const int gi = rt*64 + tx*4 + r;
        const int n = gi >> 9, i = gi & 511;
        #pragma unroll
        for (int cv = 0; cv < 4; cv++) {
            const int c = ct*64 + ty*4 + cv;
            if (c >= 1296) continue;
            float val = acc[r][cv];
            if (c < 384) {
                g_q[(size_t)gi*384 + c] = val;
            } else if (c < 768) {
                int cc = c - 384; int h = cc >> 4, d = cc & 15;
                g_kT[((size_t)(n*H_ + h)*QK_ + d)*L_ + i] = val;
            } else if (c < 1152) {
                int cc = c - 768; int h = cc >> 4, d = cc & 15;
                g_vT[((size_t)(n*H_ + h)*V_ + d)*L_ + i] = val + bv[cc];
            } else if (c < 1224) {
                int cc = c - 1152; int h = cc/3, xx = cc - h*3;
                g_a[((size_t)(n*H_ + h)*L_ + i)*3 + xx] = val + ba[cc];
            } else {
                int cc = c - 1224; int h = cc/3, xx = cc - h*3;
                g_b[((size_t)(n*H_ + h)*L_ + i)*3 + xx] = val + bb[cc];
            }
        }
    }
}

// ================= kernel B: ray attention =================
// 256 threads (8 warps, 255-reg budget -> NO spills), 2 rows/warp, 4 passes
// = 64 rows/block. grid (8, 24, 2). Fixed softmax max M0=4; base-2 exp.
__device__ __forceinline__ void attn_reduce_store(
    float av[16], float s, float ar0, float ar1, float ar2, float ath,
    int lane, float* __restrict__ cc, int h)
{
    #pragma unroll
    for (int k = 0; k < 4; k++) {
        const int half = 8 >> k;
        const bool up = (lane >> k) & 1;
        #pragma unroll
        for (int t = 0; t < half; t++) {
            float send = up ? av[t] : av[t + half];
            float recv = __shfl_xor_sync(0xffffffffu, send, 1 << k);
            av[t] = (up ? av[t + half] : av[t]) + recv;
        }
    }
    av[0] += __shfl_xor_sync(0xffffffffu, av[0], 16);

    #pragma unroll
    for (int off = 16; off > 0; off >>= 1) {
        s   += __shfl_xor_sync(0xffffffffu, s,   off);
        ar0 += __shfl_xor_sync(0xffffffffu, ar0, off);
        ar1 += __shfl_xor_sync(0xffffffffu, ar1, off);
        ar2 += __shfl_xor_sync(0xffffffffu, ar2, off);
        ath += __shfl_xor_sync(0xffffffffu, ath, off);
    }
    const float inv = 1.0f / s;
    if (lane < 16) {
        const int d = (int)(__brev((unsigned)lane) >> 28);
        cc[h*16 + d] = av[0] * inv;
    }
    if (lane == 0) {
        const float ra0 = ar0*inv, ra1 = ar1*inv, ra2 = ar2*inv;
        cc[384 + h*3 + 0] = ra0;
        cc[384 + h*3 + 1] = ra1;
        cc[384 + h*3 + 2] = ra2;
        cc[456 + h] = sqrtf(ra0*ra0 + ra1*ra1 + ra2*ra2);
        cc[480 + h] = ath*inv;
    }
}

__global__ void __launch_bounds__(256, 1) attn_kernel(
    const float* __restrict__ Rm, const float* __restrict__ t,
    const float* __restrict__ alpha, const float* __restrict__ beta)
{
    extern __shared__ float sm[];
    float*  ks  = sm;                       // [512][20]
    float*  vs  = sm + L_*KPAD;             // [512][20]
    float4* ts4 = (float4*)(sm + 2*L_*KPAD);

    const int tid = threadIdx.x;
    const int n = blockIdx.z, h = blockIdx.y;
    const int i0 = blockIdx.x * 64;

    const float* kb = g_kT + (size_t)(n*H_ + h)*QK_*L_;
    const float* vb = g_vT + (size_t)(n*H_ + h)*V_ *L_;
    for (int idx = tid; idx < QK_*L_; idx += 256) {
        int d = idx >> 9, j = idx & 511;
        ks[j*KPAD + d] = kb[idx];
        vs[j*KPAD + d] = vb[idx];
    }
    for (int j = tid; j < L_; j += 256) {
        const float* tp = t + (n*L_ + j)*3;
        ts4[j] = make_float4(tp[0], tp[1], tp[2], 0.f);
    }
    __syncthreads();

    // base-2 logit: p = 2^(c1*st - al*rs - be*th - 4*log2e)
    const float LOG2E = 1.44269504089f;
    const float al = log1pf(expf(alpha[h])) * 0.70710678118f * LOG2E;
    const float be = log1pf(expf(beta[h]))  * 0.70710678118f * LOG2E;
    const float c1 = 0.70710678118f * 0.25f * LOG2E;
    const float bias = -4.0f * LOG2E;
    const int warp = tid >> 5, lane = tid & 31;

    #pragma unroll 1
    for (int pass = 0; pass < 4; pass++) {
        const int iA = i0 + warp*8 + pass*2;
        const int iB = iA + 1;

        const float4* qpA = (const float4*)(g_q + (size_t)(n*L_ + iA)*(H_*QK_) + h*QK_);
        const float4 qA0 = qpA[0], qA1 = qpA[1], qA2 = qpA[2], qA3 = qpA[3];
        const float4* qpB = (const float4*)(g_q + (size_t)(n*L_ + iB)*(H_*QK_) + h*QK_);
        const float4 qB0 = qpB[0], qB1 = qpB[1], qB2 = qpB[2], qB3 = qpB[3];

        const float* RA = Rm + (size_t)(n*L_ + iA)*9;
        const float A00=RA[0],A01=RA[1],A02=RA[2],A10=RA[3],A11=RA[4],A12=RA[5],A20=RA[6],A21=RA[7],A22=RA[8];
        const float* RB = Rm + (size_t)(n*L_ + iB)*9;
        const float B00=RB[0],B01=RB[1],B02=RB[2],B10=RB[3],B11=RB[4],B12=RB[5],B20=RB[6],B21=RB[7],B22=RB[8];

        const float4 tiA = ts4[iA], tiB = ts4[iB];

        // a' = a / (|a|+eps): folds the angle denominator into the vector
        const float* apA = g_a + ((size_t)(n*H_ + h)*L_ + iA)*3;
        float aA0=apA[0], aA1=apA[1], aA2=apA[2];
        {
            const float inv = 1.0f/(sqrtf(aA0*aA0+aA1*aA1+aA2*aA2) + EPS_);
            aA0 *= inv; aA1 *= inv; aA2 *= inv;
        }
        const float* apB = g_a + ((size_t)(n*H_ + h)*L_ + iB)*3;
        float aB0=apB[0], aB1=apB[1], aB2=apB[2];
        {
            const float inv = 1.0f/(sqrtf(aB0*aB0+aB1*aB1+aB2*aB2) + EPS_);
            aB0 *= inv; aB1 *= inv; aB2 *= inv;
        }

        const float* bpA = g_b + ((size_t)(n*H_ + h)*L_ + iA)*3;
        const float* bpB = g_b + ((size_t)(n*H_ + h)*L_ + iB)*3;
        const float cA0 = A00*tiA.x + A10*tiA.y + A20*tiA.z + bpA[0];
        const float cA1 = A01*tiA.x + A11*tiA.y + A21*tiA.z + bpA[1];
        const float cA2 = A02*tiA.x + A12*tiA.y + A22*tiA.z + bpA[2];
        const float cB0 = B00*tiB.x + B10*tiB.y + B20*tiB.z + bpB[0];
        const float cB1 = B01*tiB.x + B11*tiB.y + B21*tiB.z + bpB[1];
        const float cB2 = B02*tiB.x + B12*tiB.y + B22*tiB.z + bpB[2];

        float sA=0.f, arA0=0.f, arA1=0.f, arA2=0.f, athA=0.f;
        float sB=0.f, arB0=0.f, arB1=0.f, arB2=0.f, athB=0.f;
        float avA[16], avB[16];
        #pragma unroll
        for (int d = 0; d < 16; d++) { avA[d]=0.f; avB[d]=0.f; }

        #pragma unroll 1
        for (int it = 0; it < 16; it++) {
            const int j = it*32 + lane;
            const float4 tj = ts4[j];

            const float rxA = fmaf(A20,tj.z, fmaf(A10,tj.y, fmaf(A00,tj.x, -cA0)));
            const float ryA = fmaf(A21,tj.z, fmaf(A11,tj.y, fmaf(A01,tj.x, -cA1)));
            const float rzA = fmaf(A22,tj.z, fmaf(A12,tj.y, fmaf(A02,tj.x, -cA2)));
            float rrA = fmaf(rxA,rxA, fmaf(ryA,ryA, rzA*rzA));
            rrA = fmaxf(rrA, 1e-24f);
            const float irA = rsqrt_fast(rrA);
            const float rsA = rrA * irA;
            const float rdaA = fmaf(rxA,aA0, fmaf(ryA,aA1, rzA*aA2));
            const float thA = acos_fast(rdaA * irA);

            const float rxB = fmaf(B20,tj.z, fmaf(B10,tj.y, fmaf(B00,tj.x, -cB0)));
            const float ryB = fmaf(B21,tj.z, fmaf(B11,tj.y, fmaf(B01,tj.x, -cB1)));
            const float rzB = fmaf(B22,tj.z, fmaf(B12,tj.y, fmaf(B02,tj.x, -cB2)));
            float rrB = fmaf(rxB,rxB, fmaf(ryB,ryB, rzB*rzB));
            rrB = fmaxf(rrB, 1e-24f);
            const float irB = rsqrt_fast(rrB);
            const float rsB = rrB * irB;
            const float rdaB = fmaf(rxB,aB0, fmaf(ryB,aB1, rzB*aB2));
            const float thB = acos_fast(rdaB * irB);

            const float4* kj = (const float4*)(ks + j*KPAD);
            const float4 k0 = kj[0], k1 = kj[1], k2 = kj[2], k3 = kj[3];
            float stA = qA0.x*k0.x + qA0.y*k0.y + qA0.z*k0.z + qA0.w*k0.w
                      + qA1.x*k1.x + qA1.y*k1.y + qA1.z*k1.z + qA1.w*k1.w
                      + qA2.x*k2.x + qA2.y*k2.y + qA2.z*k2.z + qA2.w*k2.w
                      + qA3.x*k3.x + qA3.y*k3.y + qA3.z*k3.z + qA3.w*k3.w;
            float stB = qB0.x*k0.x + qB0.y*k0.y + qB0.z*k0.z + qB0.w*k0.w
                      + qB1.x*k1.x + qB1.y*k1.y + qB1.z*k1.z + qB1.w*k1.w
                      + qB2.x*k2.x + qB2.y*k2.y + qB2.z*k2.z + qB2.w*k2.w
                      + qB3.x*k3.x + qB3.y*k3.y + qB3.z*k3.z + qB3.w*k3.w;

            float argA = fmaf(c1, stA, fmaf(-al, rsA, fmaf(-be, thA, bias)));
            float argB = fmaf(c1, stB, fmaf(-al, rsB, fmaf(-be, thB, bias)));
            if (j == iA) argA = -150.f;
            if (j == iB) argB = -150.f;
            const float pA = ex2_fast(argA);
            const float pB = ex2_fast(argB);

            const float4* vj = (const float4*)(vs + j*KPAD);
            const float4 v0 = vj[0], v1 = vj[1], v2 = vj[2], v3 = vj[3];

            sA += pA; sB += pB;
            avA[0]=fmaf(pA,v0.x,avA[0]); avA[1]=fmaf(pA,v0.y,avA[1]); avA[2]=fmaf(pA,v0.z,avA[2]); avA[3]=fmaf(pA,v0.w,avA[3]);
            avA[4]=fmaf(pA,v1.x,avA[4]); avA[5]=fmaf(pA,v1.y,avA[5]); avA[6]=fmaf(pA,v1.z,avA[6]); avA[7]=fmaf(pA,v1.w,avA[7]);
            avA[8]=fmaf(pA,v2.x,avA[8]); avA[9]=fmaf(pA,v2.y,avA[9]); avA[10]=fmaf(pA,v2.z,avA[10]); avA[11]=fmaf(pA,v2.w,avA[11]);
            avA[12]=fmaf(pA,v3.x,avA[12]); avA[13]=fmaf(pA,v3.y,avA[13]); avA[14]=fmaf(pA,v3.z,avA[14]); avA[15]=fmaf(pA,v3.w,avA[15]);
            avB[0]=fmaf(pB,v0.x,avB[0]); avB[1]=fmaf(pB,v0.y,avB[1]); avB[2]=fmaf(pB,v0.z,avB[2]); avB[3]=fmaf(pB,v0.w,avB[3]);
            avB[4]=fmaf(pB,v1.x,avB[4]); avB[5]=fmaf(pB,v1.y,avB[5]); avB[6]=fmaf(pB,v1.z,avB[6]); avB[7]=fmaf(pB,v1.w,avB[7]);
            avB[8]=fmaf(pB,v2.x,avB[8]); avB[9]=fmaf(pB,v2.y,avB[9]); avB[10]=fmaf(pB,v2.z,avB[10]); avB[11]=fmaf(pB,v2.w,avB[11]);
            avB[12]=fmaf(pB,v3.x,avB[12]); avB[13]=fmaf(pB,v3.y,avB[13]); avB[14]=fmaf(pB,v3.z,avB[14]); avB[15]=fmaf(pB,v3.w,avB[15]);

            arA0=fmaf(pA,rxA,arA0); arA1=fmaf(pA,ryA,arA1); arA2=fmaf(pA,rzA,arA2); athA=fmaf(pA,thA,athA);
            arB0=fmaf(pB,rxB,arB0); arB1=fmaf(pB,ryB,arB1); arB2=fmaf(pB,rzB,arB2); athB=fmaf(pB,thB,athB);
        }

        float* ccA = g_cc + (size_t)(n*L_ + iA)*CH_;
        float* ccB = g_cc + (size_t)(n*L_ + iB)*CH_;
        attn_reduce_store(avA, sA, arA0, arA1, arA2, athA, lane, ccA, h);
        attn_reduce_store(avB, sB, arB0, arB1, arB2, athB, lane, ccB, h);
    }
}

// ================= kernel C: output projection =================
__global__ void out_kernel(const float* __restrict__ Wp, const float* __restrict__ bp,
                           float* __restrict__ out)
{
    __shared__ __align__(16) float cs[8*CH_];
    const int tid = threadIdx.x;
    const int r0 = blockIdx.x * 8;

    for (int idx = tid; idx < 8*CH_; idx += 128)
        cs[idx] = g_cc[(size_t)r0*CH_ + idx];
    __syncthreads();

    float acc[8];
    #pragma unroll
    for (int r = 0; r < 8; r++) acc[r] = 0.f;

    const float4* w4 = (const float4*)(Wp + (size_t)tid*CH_);
    #pragma unroll 2
    for (int k4 = 0; k4 < CH_/4; k4++) {
        const float4 w = w4[k4];
        #pragma unroll
        for (int r = 0; r < 8; r++) {
            const float4 cv = ((const float4*)(cs + r*CH_))[k4];
            acc[r] += cv.x*w.x + cv.y*w.y + cv.z*w.z + cv.w*w.w;
        }
    }
    const float bbv = bp[tid];
    #pragma unroll
    for (int r = 0; r < 8; r++)
        out[(size_t)(r0 + r)*HID_ + tid] = acc[r] + bbv;
}

// ---------------- launch ----------------
extern "C" void kernel_launch(void* const* d_in, const int* in_sizes, int n_in,
                              void* d_out, int out_size)
{
    const float* x     = (const float*)d_in[0];
    const float* R     = (const float*)d_in[1];
    const float* t     = (const float*)d_in[2];
    const float* Wq    = (const float*)d_in[4];
    const float* Wk    = (const float*)d_in[5];
    const float* Wv    = (const float*)d_in[6];
    const float* bv    = (const float*)d_in[7];
    const float* Wa    = (const float*)d_in[8];
    const float* ba    = (const float*)d_in[9];
    const float* Wb    = (const float*)d_in[10];
    const float* bb    = (const float*)d_in[11];
    const float* Wp    = (const float*)d_in[12];
    const float* bp    = (const float*)d_in[13];
    const float* alpha = (const float*)d_in[14];
    const float* beta  = (const float*)d_in[15];

    proj_kernel<<<dim3(16, 21), 256>>>(x, Wq, Wk, Wv, bv, Wa, ba, Wb, bb);

    const int smem = (2*L_*KPAD + L_*4) * (int)sizeof(float);  // 90112 B
    cudaFuncSetAttribute(attn_kernel, cudaFuncAttributeMaxDynamicSharedMemorySize, smem);
    attn_kernel<<<dim3(8, H_, N_), 256, smem>>>(R, t, alpha, beta);

    out_kernel<<<dim3(128), 128>>>(Wp, bp, (float*)d_out);
}

// round 8
// speedup vs baseline: 1.2365x; 1.0393x over previous
#include <cuda_runtime.h>
#include <math.h>

#define N_    2
#define L_    512
#define H_    24
#define QK_   16
#define V_    16
#define HID_  128
#define CH_   504
#define EPS_  1e-6f
#define KPAD  20

// ---------------- scratch ----------------
__device__ float g_q [N_*L_*H_*QK_];   // [n*L+i][h*16+d]
__device__ float g_kT[N_*H_*QK_*L_];   // [n][h][d][j]
__device__ float g_vT[N_*H_*V_ *L_];   // [n][h][d][j]
__device__ float g_a [N_*H_*L_*3];
__device__ float g_b [N_*H_*L_*3];
__device__ float g_cc[N_*L_*CH_];

__device__ __forceinline__ float rsqrt_fast(float x) {
    float r; asm("rsqrt.approx.f32 %0,%1;" : "=f"(r) : "f"(x)); return r;
}
__device__ __forceinline__ float ex2_fast(float x) {
    float r; asm("ex2.approx.f32 %0,%1;" : "=f"(r) : "f"(x)); return r;
}
// fast acos with built-in clamp: A&S 4.4.45, |err| <= 6.8e-5 (budget 1e-3)
__device__ __forceinline__ float acos_fast(float x) {
    float ax = fminf(fabsf(x), 1.0f);
    float s; asm("sqrt.approx.f32 %0,%1;" : "=f"(s) : "f"(1.0f - ax));
    float p = fmaf(ax, -0.0187293f, 0.0742610f);
    p = fmaf(ax, p, -0.2121144f);
    p = fmaf(ax, p, 1.5707288f);
    float r = s * p;
    return x < 0.f ? 3.14159265359f - r : r;
}

// ================= kernel A: fused projections (proven 22-23us) =================
#define PJS 68

__global__ void __launch_bounds__(256) proj_kernel(
    const float* __restrict__ x,
    const float* __restrict__ Wq, const float* __restrict__ Wk,
    const float* __restrict__ Wv, const float* __restrict__ bv,
    const float* __restrict__ Wa, const float* __restrict__ ba,
    const float* __restrict__ Wb, const float* __restrict__ bb)
{
    __shared__ float xs[32*PJS];   // [k][m]
    __shared__ float ws[32*PJS];   // [k][c_local]

    const int tid = threadIdx.x;
    const int rt  = blockIdx.x;    // 16 row tiles of 64
    const int ct  = blockIdx.y;    // 21 col tiles of 64

    const int tx = tid & 15;
    const int ty = tid >> 4;

    float acc[4][4];
    #pragma unroll
    for (int r = 0; r < 4; r++)
        #pragma unroll
        for (int c = 0; c < 4; c++) acc[r][c] = 0.f;

    #pragma unroll 1
    for (int chunk = 0; chunk < 4; chunk++) {
        __syncthreads();
        #pragma unroll
        for (int it = 0; it < 2; it++) {
            const int idx = it*256 + tid;
            const int kq = idx & 7;
            const int m  = idx >> 3;
            const float4 v = *(const float4*)(x + (size_t)(rt*64 + m)*HID_ + chunk*32 + kq*4);
            xs[(kq*4+0)*PJS + m] = v.x;
            xs[(kq*4+1)*PJS + m] = v.y;
            xs[(kq*4+2)*PJS + m] = v.z;
            xs[(kq*4+3)*PJS + m] = v.w;
        }
        #pragma unroll
        for (int it = 0; it < 2; it++) {
            const int idx = it*256 + tid;
            const int kq = idx & 7;
            const int cl = idx >> 3;
            const int c  = min(ct*64 + cl, 1295);
            const float* wrow;
            if      (c <  384) wrow = Wq + (size_t)c*HID_;
            else if (c <  768) wrow = Wk + (size_t)(c- 384)*HID_;
            else if (c < 1152) wrow = Wv + (size_t)(c- 768)*HID_;
            else if (c < 1224) wrow = Wa + (size_t)(c-1152)*HID_;
            else               wrow = Wb + (size_t)(c-1224)*HID_;
            const float4 v = *(const float4*)(wrow + chunk*32 + kq*4);
            ws[(kq*4+0)*PJS + cl] = v.x;
            ws[(kq*4+1)*PJS + cl] = v.y;
            ws[(kq*4+2)*PJS + cl] = v.z;
            ws[(kq*4+3)*PJS + cl] = v.w;
        }
        __syncthreads();

        #pragma unroll
        for (int k = 0; k < 32; k++) {
            const float4 xv = *(const float4*)(xs + k*PJS + tx*4);
            const float4 wv = *(const float4*)(ws + k*PJS + ty*4);
            const float xa[4] = {xv.x, xv.y, xv.z, xv.w};
            const float wa[4] = {wv.x, wv.y, wv.z, wv.w};
            #pragma unroll
            for (int r = 0; r < 4; r++)
                #pragma unroll
                for (int c = 0; c < 4; c++)
                    acc[r][c] = fmaf(xa[r], wa[c], acc[r][c]);
        }
    }

    #pragma unroll
    for (int r = 0; r < 4; r++) {
        const int gi = rt*64 + tx*4 + r;
        const int n = gi >> 9, i = gi & 511;
        #pragma unroll
        for (int cv = 0; cv < 4; cv++) {
            const int c = ct*64 + ty*4 + cv;
            if (c >= 1296) continue;
            float val = acc[r][cv];
            if (c < 384) {
                g_q[(size_t)gi*384 + c] = val;
            } else if (c < 768) {
                int cc = c - 384; int h = cc >> 4, d = cc & 15;
                g_kT[((size_t)(n*H_ + h)*QK_ + d)*L_ + i] = val;
            } else if (c < 1152) {
                int cc = c - 768; int h = cc >> 4, d = cc & 15;
                g_vT[((size_t)(n*H_ + h)*V_ + d)*L_ + i] = val + bv[cc];
            } else if (c < 1224) {
                int cc = c - 1152; int h = cc/3, xx = cc - h*3;
                g_a[((size_t)(n*H_ + h)*L_ + i)*3 + xx] = val + ba[cc];
            } else {
                int cc = c - 1224; int h = cc/3, xx = cc - h*3;
                g_b[((size_t)(n*H_ + h)*L_ + i)*3 + xx] = val + bb[cc];
            }
        }
    }
}

// ================= kernel B: ray attention =================
// 256 threads, 2 rows/warp, 4 passes = 64 rows/block.
// q lives in SMEM (not regs) so regs <= 128 -> 2 blocks/SM -> 4 warps/SMSP.
#define SM_TS (2*L_*KPAD)                 // ts4 offset (floats)
#define SM_QS (SM_TS + 4*L_)              // qs offset (floats)
#define ATTN_SMEM ((SM_QS + 64*16)*4)     // 94208 B

__device__ __forceinline__ void attn_reduce_store(
    float av[16], float s, float ar0, float ar1, float ar2, float ath,
    int lane, float* __restrict__ cc, int h)
{
    #pragma unroll
    for (int k = 0; k < 4; k++) {
        const int half = 8 >> k;
        const bool up = (lane >> k) & 1;
        #pragma unroll
        for (int t = 0; t < half; t++) {
            float send = up ? av[t] : av[t + half];
            float recv = __shfl_xor_sync(0xffffffffu, send, 1 << k);
            av[t] = (up ? av[t + half] : av[t]) + recv;
        }
    }
    av[0] += __shfl_xor_sync(0xffffffffu, av[0], 16);

    #pragma unroll
    for (int off = 16; off > 0; off >>= 1) {
        s   += __shfl_xor_sync(0xffffffffu, s,   off);
        ar0 += __shfl_xor_sync(0xffffffffu, ar0, off);
        ar1 += __shfl_xor_sync(0xffffffffu, ar1, off);
        ar2 += __shfl_xor_sync(0xffffffffu, ar2, off);
        ath += __shfl_xor_sync(0xffffffffu, ath, off);
    }
    const float inv = 1.0f / s;
    if (lane < 16) {
        const int d = (int)(__brev((unsigned)lane) >> 28);
        cc[h*16 + d] = av[0] * inv;
    }
    if (lane == 0) {
        const float ra0 = ar0*inv, ra1 = ar1*inv, ra2 = ar2*inv;
        cc[384 + h*3 + 0] = ra0;
        cc[384 + h*3 + 1] = ra1;
        cc[384 + h*3 + 2] = ra2;
        cc[456 + h] = sqrtf(ra0*ra0 + ra1*ra1 + ra2*ra2);
        cc[480 + h] = ath*inv;
    }
}

__global__ void __launch_bounds__(256, 2) attn_kernel(
    const float* __restrict__ Rm, const float* __restrict__ t,
    const float* __restrict__ alpha, const float* __restrict__ beta)
{
    extern __shared__ float sm[];
    float*  ks  = sm;                       // [512][20]
    float*  vs  = sm + L_*KPAD;             // [512][20]
    float4* ts4 = (float4*)(sm + SM_TS);    // [512]
    float*  qs  = sm + SM_QS;               // [64][16]

    const int tid = threadIdx.x;
    const int n = blockIdx.z, h = blockIdx.y;
    const int i0 = blockIdx.x * 64;

    const float* kb = g_kT + (size_t)(n*H_ + h)*QK_*L_;
    const float* vb = g_vT + (size_t)(n*H_ + h)*V_ *L_;
    for (int idx = tid; idx < QK_*L_; idx += 256) {
        int d = idx >> 9, j = idx & 511;
        ks[j*KPAD + d] = kb[idx];
        vs[j*KPAD + d] = vb[idx];
    }
    for (int j = tid; j < L_; j += 256) {
        const float* tp = t + (n*L_ + j)*3;
        ts4[j] = make_float4(tp[0], tp[1], tp[2], 0.f);
    }
    {   // q tile for the 64 rows of this block: one float4 per thread
        const int row = tid >> 2, dq = tid & 3;
        const float4 qv = *(const float4*)(g_q + (size_t)(n*L_ + i0 + row)*(H_*QK_) + h*QK_ + dq*4);
        *(float4*)(qs + row*16 + dq*4) = qv;
    }
    __syncthreads();

    const float LOG2E = 1.44269504089f;
    const float al = log1pf(expf(alpha[h])) * 0.70710678118f * LOG2E;
    const float be = log1pf(expf(beta[h]))  * 0.70710678118f * LOG2E;
    const float c1 = 0.70710678118f * 0.25f * LOG2E;
    const float bias = -4.0f * LOG2E;
    const int warp = tid >> 5, lane = tid & 31;

    #pragma unroll 1
    for (int pass = 0; pass < 4; pass++) {
        const int iA = i0 + warp*8 + pass*2;
        const int iB = iA + 1;
        const float* qsA = qs + (warp*8 + pass*2)*16;
        const float* qsB = qsA + 16;

        const float* RA = Rm + (size_t)(n*L_ + iA)*9;
        const float A00=RA[0],A01=RA[1],A02=RA[2],A10=RA[3],A11=RA[4],A12=RA[5],A20=RA[6],A21=RA[7],A22=RA[8];
        const float* RB = Rm + (size_t)(n*L_ + iB)*9;
        const float B00=RB[0],B01=RB[1],B02=RB[2],B10=RB[3],B11=RB[4],B12=RB[5],B20=RB[6],B21=RB[7],B22=RB[8];

        const float4 tiA = ts4[iA - i0 + i0]; // i is global; ts4 indexed globally
        const float4 tiB = ts4[iB];
        const float4 tiAv = ts4[iA];

        const float* apA = g_a + ((size_t)(n*H_ + h)*L_ + iA)*3;
        float aA0=apA[0], aA1=apA[1], aA2=apA[2];
        {
            const float inv = 1.0f/(sqrtf(aA0*aA0+aA1*aA1+aA2*aA2) + EPS_);
            aA0 *= inv; aA1 *= inv; aA2 *= inv;
        }
        const float* apB = g_a + ((size_t)(n*H_ + h)*L_ + iB)*3;
        float aB0=apB[0], aB1=apB[1], aB2=apB[2];
        {
            const float inv = 1.0f/(sqrtf(aB0*aB0+aB1*aB1+aB2*aB2) + EPS_);
            aB0 *= inv; aB1 *= inv; aB2 *= inv;
        }

        const float* bpA = g_b + ((size_t)(n*H_ + h)*L_ + iA)*3;
        const float* bpB = g_b + ((size_t)(n*H_ + h)*L_ + iB)*3;
        const float cA0 = A00*tiAv.x + A10*tiAv.y + A20*tiAv.z + bpA[0];
        const float cA1 = A01*tiAv.x + A11*tiAv.y + A21*tiAv.z + bpA[1];
        const float cA2 = A02*tiAv.x + A12*tiAv.y + A22*tiAv.z + bpA[2];
        const float cB0 = B00*tiB.x + B10*tiB.y + B20*tiB.z + bpB[0];
        const float cB1 = B01*tiB.x + B11*tiB.y + B21*tiB.z + bpB[1];
        const float cB2 = B02*tiB.x + B12*tiB.y + B22*tiB.z + bpB[2];

        float sA=0.f, arA0=0.f, arA1=0.f, arA2=0.f, athA=0.f;
        float sB=0.f, arB0=0.f, arB1=0.f, arB2=0.f, athB=0.f;
        float avA[16], avB[16];
        #pragma unroll
        for (int d = 0; d < 16; d++) { avA[d]=0.f; avB[d]=0.f; }

        #pragma unroll 1
        for (int it = 0; it < 16; it++) {
            const int j = it*32 + lane;
            const float4 tj = ts4[j];

            const float rxA = fmaf(A20,tj.z, fmaf(A10,tj.y, fmaf(A00,tj.x, -cA0)));
            const float ryA = fmaf(A21,tj.z, fmaf(A11,tj.y, fmaf(A01,tj.x, -cA1)));
            const float rzA = fmaf(A22,tj.z, fmaf(A12,tj.y, fmaf(A02,tj.x, -cA2)));
            float rrA = fmaf(rxA,rxA, fmaf(ryA,ryA, rzA*rzA));
            rrA = fmaxf(rrA, 1e-24f);
            const float irA = rsqrt_fast(rrA);
            const float rsA = rrA * irA;
            const float rdaA = fmaf(rxA,aA0, fmaf(ryA,aA1, rzA*aA2));
            const float thA = acos_fast(rdaA * irA);

            const float rxB = fmaf(B20,tj.z, fmaf(B10,tj.y, fmaf(B00,tj.x, -cB0)));
            const float ryB = fmaf(B21,tj.z, fmaf(B11,tj.y, fmaf(B01,tj.x, -cB1)));
            const float rzB = fmaf(B22,tj.z, fmaf(B12,tj.y, fmaf(B02,tj.x, -cB2)));
            float rrB = fmaf(rxB,rxB, fmaf(ryB,ryB, rzB*rzB));
            rrB = fmaxf(rrB, 1e-24f);
            const float irB = rsqrt_fast(rrB);
            const float rsB = rrB * irB;
            const float rdaB = fmaf(rxB,aB0, fmaf(ryB,aB1, rzB*aB2));
            const float thB = acos_fast(rdaB * irB);

            const float4* kj = (const float4*)(ks + j*KPAD);
            const float4 k0 = kj[0], k1 = kj[1], k2 = kj[2], k3 = kj[3];
            const float4 qA0 = *(const float4*)(qsA +  0);
            const float4 qA1 = *(const float4*)(qsA +  4);
            const float4 qA2 = *(const float4*)(qsA +  8);
            const float4 qA3 = *(const float4*)(qsA + 12);
            float stA = qA0.x*k0.x + qA0.y*k0.y + qA0.z*k0.z + qA0.w*k0.w
                      + qA1.x*k1.x + qA1.y*k1.y + qA1.z*k1.z + qA1.w*k1.w
                      + qA2.x*k2.x + qA2.y*k2.y + qA2.z*k2.z + qA2.w*k2.w
                      + qA3.x*k3.x + qA3.y*k3.y + qA3.z*k3.z + qA3.w*k3.w;
            const float4 qB0 = *(const float4*)(qsB +  0);
            const float4 qB1 = *(const float4*)(qsB +  4);
            const float4 qB2 = *(const float4*)(qsB +  8);
            const float4 qB3 = *(const float4*)(qsB + 12);
            float stB = qB0.x*k0.x + qB0.y*k0.y + qB0.z*k0.z + qB0.w*k0.w
                      + qB1.x*k1.x + qB1.y*k1.y + qB1.z*k1.z + qB1.w*k1.w
                      + qB2.x*k2.x + qB2.y*k2.y + qB2.z*k2.z + qB2.w*k2.w
                      + qB3.x*k3.x + qB3.y*k3.y + qB3.z*k3.z + qB3.w*k3.w;

            float argA = fmaf(c1, stA, fmaf(-al, rsA, fmaf(-be, thA, bias)));
            float argB = fmaf(c1, stB, fmaf(-al, rsB, fmaf(-be, thB, bias)));
            if (j == iA) argA = -150.f;
            if (j == iB) argB = -150.f;
            const float pA = ex2_fast(argA);
            const float pB = ex2_fast(argB);

            const float4* vj = (const float4*)(vs + j*KPAD);
            const float4 v0 = vj[0], v1 = vj[1], v2 = vj[2], v3 = vj[3];

            sA += pA; sB += pB;
            avA[0]=fmaf(pA,v0.x,avA[0]); avA[1]=fmaf(pA,v0.y,avA[1]); avA[2]=fmaf(pA,v0.z,avA[2]); avA[3]=fmaf(pA,v0.w,avA[3]);
            avA[4]=fmaf(pA,v1.x,avA[4]); avA[5]=fmaf(pA,v1.y,avA[5]); avA[6]=fmaf(pA,v1.z,avA[6]); avA[7]=fmaf(pA,v1.w,avA[7]);
            avA[8]=fmaf(pA,v2.x,avA[8]); avA[9]=fmaf(pA,v2.y,avA[9]); avA[10]=fmaf(pA,v2.z,avA[10]); avA[11]=fmaf(pA,v2.w,avA[11]);
            avA[12]=fmaf(pA,v3.x,avA[12]); avA[13]=fmaf(pA,v3.y,avA[13]); avA[14]=fmaf(pA,v3.z,avA[14]); avA[15]=fmaf(pA,v3.w,avA[15]);
            avB[0]=fmaf(pB,v0.x,avB[0]); avB[1]=fmaf(pB,v0.y,avB[1]); avB[2]=fmaf(pB,v0.z,avB[2]); avB[3]=fmaf(pB,v0.w,avB[3]);
            avB[4]=fmaf(pB,v1.x,avB[4]); avB[5]=fmaf(pB,v1.y,avB[5]); avB[6]=fmaf(pB,v1.z,avB[6]); avB[7]=fmaf(pB,v1.w,avB[7]);
            avB[8]=fmaf(pB,v2.x,avB[8]); avB[9]=fmaf(pB,v2.y,avB[9]); avB[10]=fmaf(pB,v2.z,avB[10]); avB[11]=fmaf(pB,v2.w,avB[11]);
            avB[12]=fmaf(pB,v3.x,avB[12]); avB[13]=fmaf(pB,v3.y,avB[13]); avB[14]=fmaf(pB,v3.z,avB[14]); avB[15]=fmaf(pB,v3.w,avB[15]);

            arA0=fmaf(pA,rxA,arA0); arA1=fmaf(pA,ryA,arA1); arA2=fmaf(pA,rzA,arA2); athA=fmaf(pA,thA,athA);
            arB0=fmaf(pB,rxB,arB0); arB1=fmaf(pB,ryB,arB1); arB2=fmaf(pB,rzB,arB2); athB=fmaf(pB,thB,athB);
        }

        float* ccA = g_cc + (size_t)(n*L_ + iA)*CH_;
        float* ccB = g_cc + (size_t)(n*L_ + iB)*CH_;
        attn_reduce_store(avA, sA, arA0, arA1, arA2, athA, lane, ccA, h);
        attn_reduce_store(avB, sB, arB0, arB1, arB2, athB, lane, ccB, h);
    }
}

// ================= kernel C: output projection =================
__global__ void out_kernel(const float* __restrict__ Wp, const float* __restrict__ bp,
                           float* __restrict__ out)
{
    __shared__ __align__(16) float cs[8*CH_];
    const int tid = threadIdx.x;
    const int r0 = blockIdx.x * 8;

    for (int idx = tid; idx < 8*CH_; idx += 128)
        cs[idx] = g_cc[(size_t)r0*CH_ + idx];
    __syncthreads();

    float acc[8];
    #pragma unroll
    for (int r = 0; r < 8; r++) acc[r] = 0.f;

    const float4* w4 = (const float4*)(Wp + (size_t)tid*CH_);
    #pragma unroll 2
    for (int k4 = 0; k4 < CH_/4; k4++) {
        const float4 w = w4[k4];
        #pragma unroll
        for (int r = 0; r < 8; r++) {
            const float4 cv = ((const float4*)(cs + r*CH_))[k4];
            acc[r] += cv.x*w.x + cv.y*w.y + cv.z*w.z + cv.w*w.w;
        }
    }
    const float bbv = bp[tid];
    #pragma unroll
    for (int r = 0; r < 8; r++)
        out[(size_t)(r0 + r)*HID_ + tid] = acc[r] + bbv;
}

// ---------------- launch ----------------
extern "C" void kernel_launch(void* const* d_in, const int* in_sizes, int n_in,
                              void* d_out, int out_size)
{
    const float* x     = (const float*)d_in[0];
    const float* R     = (const float*)d_in[1];
    const float* t     = (const float*)d_in[2];
    const float* Wq    = (const float*)d_in[4];
    const float* Wk    = (const float*)d_in[5];
    const float* Wv    = (const float*)d_in[6];
    const float* bv    = (const float*)d_in[7];
    const float* Wa    = (const float*)d_in[8];
    const float* ba    = (const float*)d_in[9];
    const float* Wb    = (const float*)d_in[10];
    const float* bb    = (const float*)d_in[11];
    const float* Wp    = (const float*)d_in[12];
    const float* bp    = (const float*)d_in[13];
    const float* alpha = (const float*)d_in[14];
    const float* beta  = (const float*)d_in[15];

    proj_kernel<<<dim3(16, 21), 256>>>(x, Wq, Wk, Wv, bv, Wa, ba, Wb, bb);

    cudaFuncSetAttribute(attn_kernel, cudaFuncAttributeMaxDynamicSharedMemorySize, ATTN_SMEM);
    attn_kernel<<<dim3(8, H_, N_), 256, ATTN_SMEM>>>(R, t, alpha, beta);

    out_kernel<<<dim3(128), 128>>>(Wp, bp, (float*)d_out);
}